// round 4
// baseline (speedup 1.0000x reference)
#include <cuda_runtime.h>
#include <cuda_bf16.h>

// GivensRotationPerHead: H=64 heads, DIM=128, R=8128 rotations (triu i-major order).
// Round 4:
//   - givens_half_kernel unchanged from R3 (passing, ~19us).
//   - combine_kernel rewritten: conflict-free lane mapping, double-buffered
//     k-chunks, packed fma.rn.f32x2 (sm_100a) -> target ~6us (was 26us).

#define NHEADS 64
#define DIMN   128
#define NROT   8128
#define TPB    128

#define SPLIT_I   40
#define SPLIT_B   5
#define NB        16
#define R_SPLIT   4300
#define RANGE0    4300
#define RANGE1    3828
#define MAXRANGE  4300

__device__ __forceinline__ int rbase(int i) { return i * 127 - (i * (i - 1)) / 2; }
__device__ __forceinline__ int blockbase8(int b) { return 988 * b - 32 * b * (b - 1); }

__device__ __forceinline__ void frot(float& vi, float& vj, float a, float b) {
    float ni = fmaf(a, vj, vi);
    vj = fmaf(b, vi, vj);
    vi = ni;
}

// 8 MB global scratch: halfQ[task][128][128], task = head*2 + half
__device__ float g_halfQ[2 * NHEADS * DIMN * DIMN];

#define OFF_T   MAXRANGE
#define OFF_FI  (2 * MAXRANGE)
#define OFF_FJ  (3 * MAXRANGE)
#define OFF_AB  (4 * MAXRANGE)
#define OFF_RS  (4 * MAXRANGE + 2 * MAXRANGE)
#define SM_FLOATS (OFF_RS + DIMN)     // 25928 floats = 103712 B

__global__ __launch_bounds__(TPB)
void givens_half_kernel(const float* __restrict__ thetas,
                        const int*   __restrict__ rot_i,
                        const int*   __restrict__ rot_j)
{
    extern __shared__ float sm[];
    float*  C  = sm;
    float*  T  = sm + OFF_T;
    float*  Fi = sm + OFF_FI;
    float*  Fj = sm + OFF_FJ;
    float*  Qs = sm;                         // aliases C/T/Fi after pass 3
    float2* AB = (float2*)(sm + OFF_AB);
    float*  rs = sm + OFF_RS;

    const int tid  = threadIdx.x;
    const int task = blockIdx.x;
    const int head = task >> 1;
    const int half = task & 1;

    const int r0    = half ? R_SPLIT : 0;
    const int range = half ? RANGE1 : RANGE0;
    const int b_lo  = half ? SPLIT_B : 0;
    const int b_hi  = half ? NB : SPLIT_B;
    const int ilo   = half ? SPLIT_I : 0;
    const int ihi   = half ? DIMN : SPLIT_I;

    const float* th = thetas + (size_t)head * NROT + r0;

    // ---- pass 1: cos / tan ----
    for (int rl = tid; rl < range; rl += TPB) {
        float s, c;
        __sincosf(th[rl], &s, &c);
        C[rl] = c;
        T[rl] = __fdividef(s, c);
    }
    __syncthreads();

    // ---- pass 2: per-row prefix products (row = tid) ----
    {
        const int m = tid;
        float f = 1.0f;
        int kend = m < ihi ? m : ihi;
        for (int k = ilo; k < kend; ++k) {
            int rl = rbase(k) + (m - k - 1) - r0;
            Fj[rl] = f;
            f *= C[rl];
        }
        if (m >= ilo && m < ihi) {
            int base = rbase(m) - r0;
            for (int j = m + 1; j < DIMN; ++j) {
                int rl = base + (j - m - 1);
                Fi[rl] = f;
                f *= C[rl];
            }
        }
        rs[m] = f;
    }
    __syncthreads();

    // ---- pass 3: alpha/beta into blocked AB table ----
    for (int rl = tid; rl < range; rl += TPB) {
        int r = r0 + rl;
        int i = rot_i[r];
        int j = rot_j[r];
        float t  = T[rl];
        float fi = Fi[rl];
        float fj = Fj[rl];
        float al =  t * __fdividef(fj, fi);
        float be = -t * __fdividef(fi, fj);
        int b  = i >> 3;
        int a  = i & 7;
        int i0 = b << 3;
        int bb = blockbase8(b) - r0;
        int pos;
        if (j < i0 + 8) {
            int jj = j - i0;
            pos = bb + a * 7 - (a * (a - 1)) / 2 + (jj - a - 1);
        } else {
            pos = bb + 28 + ((j - i0 - 8) << 3) + a;
        }
        AB[pos] = make_float2(al, be);
    }
    __syncthreads();

    // ---- init Q~ = I ----
    for (int idx = tid; idx < DIMN * DIMN; idx += TPB)
        Qs[idx] = ((idx >> 7) == (idx & 127)) ? 1.0f : 0.0f;
    __syncthreads();

    // ---- main loop: 8-row register blocks, thread t = column t ----
    {
        const int t = tid;
        for (int b = b_lo; b < b_hi; ++b) {
            const int i0 = b << 3;
            const int bb = blockbase8(b) - r0;

            float v[8];
            #pragma unroll
            for (int a = 0; a < 8; ++a) v[a] = Qs[(i0 + a) * DIMN + t];

            {
                const float2* abt = AB + bb;
                int p = 0;
                #pragma unroll
                for (int a = 0; a < 7; ++a)
                    #pragma unroll
                    for (int jj = a + 1; jj < 8; ++jj) {
                        float2 ab = abt[p++];
                        frot(v[a], v[jj], ab.x, ab.y);
                    }
            }

            if (i0 + 8 < DIMN) {
                int j = i0 + 8;
                float vj = Qs[j * DIMN + t];
                const float4* ap = (const float4*)(AB + bb + 28);
                float4 a0 = ap[0], a1 = ap[1], a2 = ap[2], a3 = ap[3];

                #pragma unroll 2
                for (; j < DIMN; ++j) {
                    int jn = (j + 1 < DIMN) ? j + 1 : j;
                    const float4* np =
                        (const float4*)(AB + bb + 28 + ((jn - i0 - 8) << 3));
                    float4 n0 = np[0], n1 = np[1], n2 = np[2], n3 = np[3];
                    float  vn = Qs[jn * DIMN + t];

                    frot(v[0], vj, a0.x, a0.y);
                    frot(v[1], vj, a0.z, a0.w);
                    frot(v[2], vj, a1.x, a1.y);
                    frot(v[3], vj, a1.z, a1.w);
                    frot(v[4], vj, a2.x, a2.y);
                    frot(v[5], vj, a2.z, a2.w);
                    frot(v[6], vj, a3.x, a3.y);
                    frot(v[7], vj, a3.z, a3.w);

                    Qs[j * DIMN + t] = vj;
                    vj = vn;
                    a0 = n0; a1 = n1; a2 = n2; a3 = n3;
                }
            }

            #pragma unroll
            for (int a = 0; a < 8; ++a) Qs[(i0 + a) * DIMN + t] = v[a];
        }
    }
    __syncthreads();

    // ---- write scaled half to global scratch ----
    float* o = g_halfQ + (size_t)task * DIMN * DIMN;
    for (int idx = tid; idx < DIMN * DIMN; idx += TPB)
        o[idx] = rs[idx >> 7] * Qs[idx];
}

// ============================================================================
// Combine GEMM: out[head] = H1 @ H0, CTA = 64 rows x 128 cols.
// warp = 8 rows, lane = 4 cols (conflict-free), double-buffered k-chunks,
// packed fma.rn.f32x2.
// ============================================================================
#define GTPB 256
#define GSM_FLOATS (DIMN * DIMN + 64 * DIMN)   // sA 16384 + sB 8192 floats

#define PACK2(d, x, y) \
    asm("mov.b64 %0, {%1, %2};" : "=l"(d) : "r"(__float_as_uint(x)), "r"(__float_as_uint(y)))
#define PACK2S(d, x) \
    asm("mov.b64 %0, {%1, %1};" : "=l"(d) : "r"(__float_as_uint(x)))
#define UNPACK2(x, y, d) \
    asm("mov.b64 {%0, %1}, %2;" : "=r"(x), "=r"(y) : "l"(d))
#define FMA2(d, a, b, c) \
    asm("fma.rn.f32x2 %0, %1, %2, %3;" : "=l"(d) : "l"(a), "l"(b), "l"(c))

__global__ __launch_bounds__(GTPB)
void combine_kernel(float* __restrict__ out)
{
    extern __shared__ float gs[];
    float* sA = gs;                  // H0 full: [k][c]   (128x128)
    float* sB = gs + DIMN * DIMN;    // H1 rows: [r][k]   (64x128)

    const int tid  = threadIdx.x;
    const int head = blockIdx.x >> 1;
    const int rh   = blockIdx.x & 1;

    const float* A = g_halfQ + (size_t)(head * 2 + 0) * DIMN * DIMN;
    const float* B = g_halfQ + (size_t)(head * 2 + 1) * DIMN * DIMN
                   + (size_t)rh * 64 * DIMN;

    for (int idx = tid; idx < DIMN * DIMN / 4; idx += GTPB)
        ((float4*)sA)[idx] = ((const float4*)A)[idx];
    for (int idx = tid; idx < 64 * DIMN / 4; idx += GTPB)
        ((float4*)sB)[idx] = ((const float4*)B)[idx];
    __syncthreads();

    const int w    = tid >> 5;       // warp 0..7 -> rows w*8..w*8+7
    const int lane = tid & 31;       // lane -> cols lane*4..lane*4+3
    const int r0   = w << 3;
    const int c0   = lane << 2;

    unsigned long long accL[8], accH[8];    // (c0,c0+1) and (c0+2,c0+3) pairs
    #pragma unroll
    for (int i = 0; i < 8; ++i) { accL[i] = 0ull; accH[i] = 0ull; }

    float4 av[2][8];   // sB[r0+i][k..k+3]  (broadcast loads)
    float4 bv[2][4];   // sA[k+kk][c0..c0+3] (lane-contiguous, conflict-free)

    // preload chunk k=0
    #pragma unroll
    for (int i = 0; i < 8; ++i)
        av[0][i] = *(const float4*)&sB[(r0 + i) * DIMN + 0];
    #pragma unroll
    for (int kk = 0; kk < 4; ++kk)
        bv[0][kk] = *(const float4*)&sA[kk * DIMN + c0];

    int buf = 0;
    for (int k = 0; k < DIMN; k += 4) {
        const int nb = buf ^ 1;
        if (k + 4 < DIMN) {
            #pragma unroll
            for (int i = 0; i < 8; ++i)
                av[nb][i] = *(const float4*)&sB[(r0 + i) * DIMN + (k + 4)];
            #pragma unroll
            for (int kk = 0; kk < 4; ++kk)
                bv[nb][kk] = *(const float4*)&sA[(k + 4 + kk) * DIMN + c0];
        }

        #pragma unroll
        for (int kk = 0; kk < 4; ++kk) {
            float4 b = bv[buf][kk];
            unsigned long long bL, bH;
            PACK2(bL, b.x, b.y);
            PACK2(bH, b.z, b.w);
            #pragma unroll
            for (int i = 0; i < 8; ++i) {
                float a = (kk == 0) ? av[buf][i].x
                        : (kk == 1) ? av[buf][i].y
                        : (kk == 2) ? av[buf][i].z
                        :             av[buf][i].w;
                unsigned long long aa;
                PACK2S(aa, a);
                FMA2(accL[i], aa, bL, accL[i]);
                FMA2(accH[i], aa, bH, accH[i]);
            }
        }
        buf = nb;
    }

    float* o = out + (size_t)head * DIMN * DIMN
             + (size_t)(rh * 64 + r0) * DIMN + c0;
    #pragma unroll
    for (int i = 0; i < 8; ++i) {
        unsigned int x0, x1, x2, x3;
        UNPACK2(x0, x1, accL[i]);
        UNPACK2(x2, x3, accH[i]);
        *(float4*)(o + i * DIMN) = make_float4(
            __uint_as_float(x0), __uint_as_float(x1),
            __uint_as_float(x2), __uint_as_float(x3));
    }
}

extern "C" void kernel_launch(void* const* d_in, const int* in_sizes, int n_in,
                              void* d_out, int out_size)
{
    const float* thetas = (const float*)d_in[0];
    const int*   ri     = (const int*)d_in[1];
    const int*   rj     = (const int*)d_in[2];
    float*       out    = (float*)d_out;

    const size_t smem1 = SM_FLOATS * sizeof(float);    // 103712 B
    const size_t smem2 = GSM_FLOATS * sizeof(float);   //  98304 B
    cudaFuncSetAttribute(givens_half_kernel,
                         cudaFuncAttributeMaxDynamicSharedMemorySize, (int)smem1);
    cudaFuncSetAttribute(combine_kernel,
                         cudaFuncAttributeMaxDynamicSharedMemorySize, (int)smem2);

    givens_half_kernel<<<2 * NHEADS, TPB, smem1>>>(thetas, ri, rj);
    combine_kernel<<<2 * NHEADS, GTPB, smem2>>>(out);
}

// round 5
// speedup vs baseline: 1.6609x; 1.6609x over previous
#include <cuda_runtime.h>
#include <cuda_bf16.h>

// GivensRotationPerHead: H=64 heads, DIM=128, R=8128 rotations (triu i-major order).
// Round 5:
//   - givens_half_kernel unchanged (passing, ~19us).
//   - combine_kernel: spill-free 8x8-per-thread fp32 GEMM, 128 threads/CTA,
//     broadcast a-loads + conflict-free b-loads. Target ~7us.

#define NHEADS 64
#define DIMN   128
#define NROT   8128
#define TPB    128

#define SPLIT_I   40
#define SPLIT_B   5
#define NB        16
#define R_SPLIT   4300
#define RANGE0    4300
#define RANGE1    3828
#define MAXRANGE  4300

__device__ __forceinline__ int rbase(int i) { return i * 127 - (i * (i - 1)) / 2; }
__device__ __forceinline__ int blockbase8(int b) { return 988 * b - 32 * b * (b - 1); }

__device__ __forceinline__ void frot(float& vi, float& vj, float a, float b) {
    float ni = fmaf(a, vj, vi);
    vj = fmaf(b, vi, vj);
    vi = ni;
}

// 8 MB global scratch: halfQ[task][128][128], task = head*2 + half
__device__ float g_halfQ[2 * NHEADS * DIMN * DIMN];

#define OFF_T   MAXRANGE
#define OFF_FI  (2 * MAXRANGE)
#define OFF_FJ  (3 * MAXRANGE)
#define OFF_AB  (4 * MAXRANGE)
#define OFF_RS  (4 * MAXRANGE + 2 * MAXRANGE)
#define SM_FLOATS (OFF_RS + DIMN)     // 25928 floats = 103712 B

__global__ __launch_bounds__(TPB)
void givens_half_kernel(const float* __restrict__ thetas,
                        const int*   __restrict__ rot_i,
                        const int*   __restrict__ rot_j)
{
    extern __shared__ float sm[];
    float*  C  = sm;
    float*  T  = sm + OFF_T;
    float*  Fi = sm + OFF_FI;
    float*  Fj = sm + OFF_FJ;
    float*  Qs = sm;                         // aliases C/T/Fi after pass 3
    float2* AB = (float2*)(sm + OFF_AB);
    float*  rs = sm + OFF_RS;

    const int tid  = threadIdx.x;
    const int task = blockIdx.x;
    const int head = task >> 1;
    const int half = task & 1;

    const int r0    = half ? R_SPLIT : 0;
    const int range = half ? RANGE1 : RANGE0;
    const int b_lo  = half ? SPLIT_B : 0;
    const int b_hi  = half ? NB : SPLIT_B;
    const int ilo   = half ? SPLIT_I : 0;
    const int ihi   = half ? DIMN : SPLIT_I;

    const float* th = thetas + (size_t)head * NROT + r0;

    // ---- pass 1: cos / tan ----
    for (int rl = tid; rl < range; rl += TPB) {
        float s, c;
        __sincosf(th[rl], &s, &c);
        C[rl] = c;
        T[rl] = __fdividef(s, c);
    }
    __syncthreads();

    // ---- pass 2: per-row prefix products (row = tid) ----
    {
        const int m = tid;
        float f = 1.0f;
        int kend = m < ihi ? m : ihi;
        for (int k = ilo; k < kend; ++k) {
            int rl = rbase(k) + (m - k - 1) - r0;
            Fj[rl] = f;
            f *= C[rl];
        }
        if (m >= ilo && m < ihi) {
            int base = rbase(m) - r0;
            for (int j = m + 1; j < DIMN; ++j) {
                int rl = base + (j - m - 1);
                Fi[rl] = f;
                f *= C[rl];
            }
        }
        rs[m] = f;
    }
    __syncthreads();

    // ---- pass 3: alpha/beta into blocked AB table ----
    for (int rl = tid; rl < range; rl += TPB) {
        int r = r0 + rl;
        int i = rot_i[r];
        int j = rot_j[r];
        float t  = T[rl];
        float fi = Fi[rl];
        float fj = Fj[rl];
        float al =  t * __fdividef(fj, fi);
        float be = -t * __fdividef(fi, fj);
        int b  = i >> 3;
        int a  = i & 7;
        int i0 = b << 3;
        int bb = blockbase8(b) - r0;
        int pos;
        if (j < i0 + 8) {
            int jj = j - i0;
            pos = bb + a * 7 - (a * (a - 1)) / 2 + (jj - a - 1);
        } else {
            pos = bb + 28 + ((j - i0 - 8) << 3) + a;
        }
        AB[pos] = make_float2(al, be);
    }
    __syncthreads();

    // ---- init Q~ = I ----
    for (int idx = tid; idx < DIMN * DIMN; idx += TPB)
        Qs[idx] = ((idx >> 7) == (idx & 127)) ? 1.0f : 0.0f;
    __syncthreads();

    // ---- main loop: 8-row register blocks, thread t = column t ----
    {
        const int t = tid;
        for (int b = b_lo; b < b_hi; ++b) {
            const int i0 = b << 3;
            const int bb = blockbase8(b) - r0;

            float v[8];
            #pragma unroll
            for (int a = 0; a < 8; ++a) v[a] = Qs[(i0 + a) * DIMN + t];

            {
                const float2* abt = AB + bb;
                int p = 0;
                #pragma unroll
                for (int a = 0; a < 7; ++a)
                    #pragma unroll
                    for (int jj = a + 1; jj < 8; ++jj) {
                        float2 ab = abt[p++];
                        frot(v[a], v[jj], ab.x, ab.y);
                    }
            }

            if (i0 + 8 < DIMN) {
                int j = i0 + 8;
                float vj = Qs[j * DIMN + t];
                const float4* ap = (const float4*)(AB + bb + 28);
                float4 a0 = ap[0], a1 = ap[1], a2 = ap[2], a3 = ap[3];

                #pragma unroll 2
                for (; j < DIMN; ++j) {
                    int jn = (j + 1 < DIMN) ? j + 1 : j;
                    const float4* np =
                        (const float4*)(AB + bb + 28 + ((jn - i0 - 8) << 3));
                    float4 n0 = np[0], n1 = np[1], n2 = np[2], n3 = np[3];
                    float  vn = Qs[jn * DIMN + t];

                    frot(v[0], vj, a0.x, a0.y);
                    frot(v[1], vj, a0.z, a0.w);
                    frot(v[2], vj, a1.x, a1.y);
                    frot(v[3], vj, a1.z, a1.w);
                    frot(v[4], vj, a2.x, a2.y);
                    frot(v[5], vj, a2.z, a2.w);
                    frot(v[6], vj, a3.x, a3.y);
                    frot(v[7], vj, a3.z, a3.w);

                    Qs[j * DIMN + t] = vj;
                    vj = vn;
                    a0 = n0; a1 = n1; a2 = n2; a3 = n3;
                }
            }

            #pragma unroll
            for (int a = 0; a < 8; ++a) Qs[(i0 + a) * DIMN + t] = v[a];
        }
    }
    __syncthreads();

    // ---- write scaled half to global scratch ----
    float* o = g_halfQ + (size_t)task * DIMN * DIMN;
    for (int idx = tid; idx < DIMN * DIMN; idx += TPB)
        o[idx] = rs[idx >> 7] * Qs[idx];
}

// ============================================================================
// Combine GEMM: out[head] = H1 @ H0.  CTA = 64 rows x 128 cols (2 CTAs/head).
// 128 threads, 8x8 per-thread tile (thread grid 8 rows x 16 cols of tiles).
// a-fragment: 8 scalar LDS (warp-broadcast); b-fragment: 2 LDS.128
// (lane-contiguous, conflict-free). 64 independent FMAs per k -> ILP hides LDS.
// ============================================================================
#define GTPB 128
#define GSM_FLOATS (DIMN * DIMN + 64 * DIMN)   // sA 16384 + sB 8192 floats

__global__ __launch_bounds__(GTPB)
void combine_kernel(float* __restrict__ out)
{
    extern __shared__ float gs[];
    float* sA = gs;                  // H0 full: [k][c]   (128x128)
    float* sB = gs + DIMN * DIMN;    // H1 rows: [r][k]   (64x128)

    const int tid  = threadIdx.x;
    const int head = blockIdx.x >> 1;
    const int rh   = blockIdx.x & 1;

    const float* A = g_halfQ + (size_t)(head * 2 + 0) * DIMN * DIMN;
    const float* B = g_halfQ + (size_t)(head * 2 + 1) * DIMN * DIMN
                   + (size_t)rh * 64 * DIMN;

    for (int idx = tid; idx < DIMN * DIMN / 4; idx += GTPB)
        ((float4*)sA)[idx] = ((const float4*)A)[idx];
    for (int idx = tid; idx < 64 * DIMN / 4; idx += GTPB)
        ((float4*)sB)[idx] = ((const float4*)B)[idx];
    __syncthreads();

    const int tx = tid & 15;         // col-tile 0..15 -> cols tx*8..tx*8+7
    const int ty = tid >> 4;         // row-tile 0..7  -> rows ty*8..ty*8+7
    const int c0 = tx << 3;
    const int r0 = ty << 3;

    float acc[8][8];
    #pragma unroll
    for (int i = 0; i < 8; ++i)
        #pragma unroll
        for (int j = 0; j < 8; ++j) acc[i][j] = 0.0f;

    #pragma unroll 2
    for (int k = 0; k < DIMN; ++k) {
        float a[8];
        #pragma unroll
        for (int i = 0; i < 8; ++i)
            a[i] = sB[(r0 + i) * DIMN + k];          // warp-broadcast
        float4 b0 = *(const float4*)&sA[k * DIMN + c0];
        float4 b1 = *(const float4*)&sA[k * DIMN + c0 + 4];
        float b[8] = { b0.x, b0.y, b0.z, b0.w, b1.x, b1.y, b1.z, b1.w };

        #pragma unroll
        for (int i = 0; i < 8; ++i)
            #pragma unroll
            for (int j = 0; j < 8; ++j)
                acc[i][j] = fmaf(a[i], b[j], acc[i][j]);
    }

    float* o = out + (size_t)head * DIMN * DIMN
             + (size_t)(rh * 64 + r0) * DIMN + c0;
    #pragma unroll
    for (int i = 0; i < 8; ++i) {
        *(float4*)(o + i * DIMN)     = make_float4(acc[i][0], acc[i][1], acc[i][2], acc[i][3]);
        *(float4*)(o + i * DIMN + 4) = make_float4(acc[i][4], acc[i][5], acc[i][6], acc[i][7]);
    }
}

extern "C" void kernel_launch(void* const* d_in, const int* in_sizes, int n_in,
                              void* d_out, int out_size)
{
    const float* thetas = (const float*)d_in[0];
    const int*   ri     = (const int*)d_in[1];
    const int*   rj     = (const int*)d_in[2];
    float*       out    = (float*)d_out;

    const size_t smem1 = SM_FLOATS * sizeof(float);    // 103712 B
    const size_t smem2 = GSM_FLOATS * sizeof(float);   //  98304 B
    cudaFuncSetAttribute(givens_half_kernel,
                         cudaFuncAttributeMaxDynamicSharedMemorySize, (int)smem1);
    cudaFuncSetAttribute(combine_kernel,
                         cudaFuncAttributeMaxDynamicSharedMemorySize, (int)smem2);

    givens_half_kernel<<<2 * NHEADS, TPB, smem1>>>(thetas, ri, rj);
    combine_kernel<<<2 * NHEADS, GTPB, smem2>>>(out);
}

// round 6
// speedup vs baseline: 1.6947x; 1.0204x over previous
#include <cuda_runtime.h>
#include <cuda_bf16.h>

// GivensRotationPerHead: H=64 heads, DIM=128, R=8128 rotations (triu i-major order).
// Round 6:
//   - Structural combine: H1 = diag(I_40, M), M 88x88 dense. So
//       out[0:40, :]  = H0[0:40, :]          (exact copy, no FLOPs)
//       out[40:, :]   = M @ H0[40:, :]       (88x128x88 GEMM, 2.1x fewer FMAs)
//     Row-balanced across the 2 CTAs/head (copy+44 rows / 44 rows).
//   - givens half1: warp 0 (cols 0-31) is exact identity -> skips main loop.

#define NHEADS 64
#define DIMN   128
#define NROT   8128
#define TPB    128

#define SPLIT_I   40
#define SPLIT_B   5
#define NB        16
#define R_SPLIT   4300
#define RANGE0    4300
#define RANGE1    3828
#define MAXRANGE  4300
#define MDIM      88        // DIMN - SPLIT_I

__device__ __forceinline__ int rbase(int i) { return i * 127 - (i * (i - 1)) / 2; }
__device__ __forceinline__ int blockbase8(int b) { return 988 * b - 32 * b * (b - 1); }

__device__ __forceinline__ void frot(float& vi, float& vj, float a, float b) {
    float ni = fmaf(a, vj, vi);
    vj = fmaf(b, vi, vj);
    vi = ni;
}

// 8 MB global scratch: halfQ[task][128][128], task = head*2 + half
__device__ float g_halfQ[2 * NHEADS * DIMN * DIMN];

#define OFF_T   MAXRANGE
#define OFF_FI  (2 * MAXRANGE)
#define OFF_FJ  (3 * MAXRANGE)
#define OFF_AB  (4 * MAXRANGE)
#define OFF_RS  (4 * MAXRANGE + 2 * MAXRANGE)
#define SM_FLOATS (OFF_RS + DIMN)     // 25928 floats = 103712 B

__global__ __launch_bounds__(TPB)
void givens_half_kernel(const float* __restrict__ thetas,
                        const int*   __restrict__ rot_i,
                        const int*   __restrict__ rot_j)
{
    extern __shared__ float sm[];
    float*  C  = sm;
    float*  T  = sm + OFF_T;
    float*  Fi = sm + OFF_FI;
    float*  Fj = sm + OFF_FJ;
    float*  Qs = sm;                         // aliases C/T/Fi after pass 3
    float2* AB = (float2*)(sm + OFF_AB);
    float*  rs = sm + OFF_RS;

    const int tid  = threadIdx.x;
    const int task = blockIdx.x;
    const int head = task >> 1;
    const int half = task & 1;

    const int r0    = half ? R_SPLIT : 0;
    const int range = half ? RANGE1 : RANGE0;
    const int b_lo  = half ? SPLIT_B : 0;
    const int b_hi  = half ? NB : SPLIT_B;
    const int ilo   = half ? SPLIT_I : 0;
    const int ihi   = half ? DIMN : SPLIT_I;

    const float* th = thetas + (size_t)head * NROT + r0;

    // ---- pass 1: cos / tan ----
    for (int rl = tid; rl < range; rl += TPB) {
        float s, c;
        __sincosf(th[rl], &s, &c);
        C[rl] = c;
        T[rl] = __fdividef(s, c);
    }
    __syncthreads();

    // ---- pass 2: per-row prefix products (row = tid) ----
    {
        const int m = tid;
        float f = 1.0f;
        int kend = m < ihi ? m : ihi;
        for (int k = ilo; k < kend; ++k) {
            int rl = rbase(k) + (m - k - 1) - r0;
            Fj[rl] = f;
            f *= C[rl];
        }
        if (m >= ilo && m < ihi) {
            int base = rbase(m) - r0;
            for (int j = m + 1; j < DIMN; ++j) {
                int rl = base + (j - m - 1);
                Fi[rl] = f;
                f *= C[rl];
            }
        }
        rs[m] = f;
    }
    __syncthreads();

    // ---- pass 3: alpha/beta into blocked AB table ----
    for (int rl = tid; rl < range; rl += TPB) {
        int r = r0 + rl;
        int i = rot_i[r];
        int j = rot_j[r];
        float t  = T[rl];
        float fi = Fi[rl];
        float fj = Fj[rl];
        float al =  t * __fdividef(fj, fi);
        float be = -t * __fdividef(fi, fj);
        int b  = i >> 3;
        int a  = i & 7;
        int i0 = b << 3;
        int bb = blockbase8(b) - r0;
        int pos;
        if (j < i0 + 8) {
            int jj = j - i0;
            pos = bb + a * 7 - (a * (a - 1)) / 2 + (jj - a - 1);
        } else {
            pos = bb + 28 + ((j - i0 - 8) << 3) + a;
        }
        AB[pos] = make_float2(al, be);
    }
    __syncthreads();

    // ---- init Q~ = I ----
    for (int idx = tid; idx < DIMN * DIMN; idx += TPB)
        Qs[idx] = ((idx >> 7) == (idx & 127)) ? 1.0f : 0.0f;
    __syncthreads();

    // ---- main loop: 8-row register blocks, thread t = column t ----
    // half1 columns < 40 are exact identity; warp 0 (cols 0-31) skips entirely.
    if (!(half && tid < 32)) {
        const int t = tid;
        for (int b = b_lo; b < b_hi; ++b) {
            const int i0 = b << 3;
            const int bb = blockbase8(b) - r0;

            float v[8];
            #pragma unroll
            for (int a = 0; a < 8; ++a) v[a] = Qs[(i0 + a) * DIMN + t];

            {
                const float2* abt = AB + bb;
                int p = 0;
                #pragma unroll
                for (int a = 0; a < 7; ++a)
                    #pragma unroll
                    for (int jj = a + 1; jj < 8; ++jj) {
                        float2 ab = abt[p++];
                        frot(v[a], v[jj], ab.x, ab.y);
                    }
            }

            if (i0 + 8 < DIMN) {
                int j = i0 + 8;
                float vj = Qs[j * DIMN + t];
                const float4* ap = (const float4*)(AB + bb + 28);
                float4 a0 = ap[0], a1 = ap[1], a2 = ap[2], a3 = ap[3];

                #pragma unroll 2
                for (; j < DIMN; ++j) {
                    int jn = (j + 1 < DIMN) ? j + 1 : j;
                    const float4* np =
                        (const float4*)(AB + bb + 28 + ((jn - i0 - 8) << 3));
                    float4 n0 = np[0], n1 = np[1], n2 = np[2], n3 = np[3];
                    float  vn = Qs[jn * DIMN + t];

                    frot(v[0], vj, a0.x, a0.y);
                    frot(v[1], vj, a0.z, a0.w);
                    frot(v[2], vj, a1.x, a1.y);
                    frot(v[3], vj, a1.z, a1.w);
                    frot(v[4], vj, a2.x, a2.y);
                    frot(v[5], vj, a2.z, a2.w);
                    frot(v[6], vj, a3.x, a3.y);
                    frot(v[7], vj, a3.z, a3.w);

                    Qs[j * DIMN + t] = vj;
                    vj = vn;
                    a0 = n0; a1 = n1; a2 = n2; a3 = n3;
                }
            }

            #pragma unroll
            for (int a = 0; a < 8; ++a) Qs[(i0 + a) * DIMN + t] = v[a];
        }
    }
    __syncthreads();

    // ---- write scaled half to global scratch ----
    float* o = g_halfQ + (size_t)task * DIMN * DIMN;
    for (int idx = tid; idx < DIMN * DIMN; idx += TPB)
        o[idx] = rs[idx >> 7] * Qs[idx];
}

// ============================================================================
// Structural combine:
//   out[0:40, :] = H0[0:40, :]                 (copy, done by rh=0 CTA)
//   out[40+mb : 40+mb+44, :] = M[mb:mb+44, :] @ H0[40:, :]   (mb = rh*44)
// CTA: 256 threads, per-thread 3x8 tile over 44 GEMM rows (sM padded to 48).
// ============================================================================
#define GTPB 256
// sB = H0 rows 40..127 [88][128]; sM = M slice padded [48][88]
#define GSM_FLOATS (MDIM * DIMN + 48 * MDIM)    // 11264 + 4224 = 15488 floats

__global__ __launch_bounds__(GTPB)
void combine_kernel(float* __restrict__ out)
{
    extern __shared__ float gs[];
    float* sB = gs;                    // [kb][c], kb = global row 40+kb
    float* sM = gs + MDIM * DIMN;      // [m][k], rows 44..47 zero

    const int tid  = threadIdx.x;
    const int head = blockIdx.x >> 1;
    const int rh   = blockIdx.x & 1;
    const int mb   = rh * 44;

    const float* A = g_halfQ + (size_t)(head * 2 + 0) * DIMN * DIMN;  // H0
    const float* B = g_halfQ + (size_t)(head * 2 + 1) * DIMN * DIMN;  // H1
    float*       O = out + (size_t)head * DIMN * DIMN;

    // sB: H0[40:128][:] = 2816 float4
    {
        const float4* src = (const float4*)(A + 40 * DIMN);
        for (int i = tid; i < MDIM * DIMN / 4; i += GTPB)
            ((float4*)sB)[i] = src[i];
    }
    // zero pad rows 44..47 of sM
    for (int i = tid; i < 4 * MDIM; i += GTPB)
        sM[44 * MDIM + i] = 0.0f;
    // sM rows 0..43: M[mb+m][k] = H1[(40+mb+m)][40+k], 22 float4 per row
    for (int i = tid; i < 44 * 22; i += GTPB) {
        int m = i / 22, k4 = i % 22;
        ((float4*)(sM + m * MDIM))[k4] =
            *(const float4*)(B + (size_t)(40 + mb + m) * DIMN + 40 + k4 * 4);
    }
    // rh=0 CTA also copies out rows 0..39 (global->global, exact)
    if (rh == 0) {
        const float4* src = (const float4*)A;
        float4* dst = (float4*)O;
        for (int i = tid; i < 40 * DIMN / 4; i += GTPB)
            dst[i] = src[i];
    }
    __syncthreads();

    // GEMM: 44 rows x 128 cols, K=88. Thread grid 16x16, tile 3 rows x 8 cols.
    const int tx = tid & 15;
    const int ty = tid >> 4;
    const int c0 = tx << 3;
    const int m0 = ty * 3;

    float acc[3][8];
    #pragma unroll
    for (int i = 0; i < 3; ++i)
        #pragma unroll
        for (int j = 0; j < 8; ++j) acc[i][j] = 0.0f;

    float a0 = sM[(m0 + 0) * MDIM];
    float a1 = sM[(m0 + 1) * MDIM];
    float a2 = sM[(m0 + 2) * MDIM];
    float4 b0 = *(const float4*)&sB[c0];
    float4 b1 = *(const float4*)&sB[c0 + 4];

    #pragma unroll 2
    for (int k = 0; k < MDIM; ++k) {
        int kn = (k + 1 < MDIM) ? k + 1 : k;
        float na0 = sM[(m0 + 0) * MDIM + kn];
        float na1 = sM[(m0 + 1) * MDIM + kn];
        float na2 = sM[(m0 + 2) * MDIM + kn];
        float4 nb0 = *(const float4*)&sB[kn * DIMN + c0];
        float4 nb1 = *(const float4*)&sB[kn * DIMN + c0 + 4];

        acc[0][0] = fmaf(a0, b0.x, acc[0][0]);
        acc[0][1] = fmaf(a0, b0.y, acc[0][1]);
        acc[0][2] = fmaf(a0, b0.z, acc[0][2]);
        acc[0][3] = fmaf(a0, b0.w, acc[0][3]);
        acc[0][4] = fmaf(a0, b1.x, acc[0][4]);
        acc[0][5] = fmaf(a0, b1.y, acc[0][5]);
        acc[0][6] = fmaf(a0, b1.z, acc[0][6]);
        acc[0][7] = fmaf(a0, b1.w, acc[0][7]);

        acc[1][0] = fmaf(a1, b0.x, acc[1][0]);
        acc[1][1] = fmaf(a1, b0.y, acc[1][1]);
        acc[1][2] = fmaf(a1, b0.z, acc[1][2]);
        acc[1][3] = fmaf(a1, b0.w, acc[1][3]);
        acc[1][4] = fmaf(a1, b1.x, acc[1][4]);
        acc[1][5] = fmaf(a1, b1.y, acc[1][5]);
        acc[1][6] = fmaf(a1, b1.z, acc[1][6]);
        acc[1][7] = fmaf(a1, b1.w, acc[1][7]);

        acc[2][0] = fmaf(a2, b0.x, acc[2][0]);
        acc[2][1] = fmaf(a2, b0.y, acc[2][1]);
        acc[2][2] = fmaf(a2, b0.z, acc[2][2]);
        acc[2][3] = fmaf(a2, b0.w, acc[2][3]);
        acc[2][4] = fmaf(a2, b1.x, acc[2][4]);
        acc[2][5] = fmaf(a2, b1.y, acc[2][5]);
        acc[2][6] = fmaf(a2, b1.z, acc[2][6]);
        acc[2][7] = fmaf(a2, b1.w, acc[2][7]);

        a0 = na0; a1 = na1; a2 = na2;
        b0 = nb0; b1 = nb1;
    }

    const int rowbase = 40 + mb;
    #pragma unroll
    for (int i = 0; i < 3; ++i) {
        int m = m0 + i;
        if (m < 44) {
            float* o = O + (size_t)(rowbase + m) * DIMN + c0;
            *(float4*)o       = make_float4(acc[i][0], acc[i][1], acc[i][2], acc[i][3]);
            *(float4*)(o + 4) = make_float4(acc[i][4], acc[i][5], acc[i][6], acc[i][7]);
        }
    }
}

extern "C" void kernel_launch(void* const* d_in, const int* in_sizes, int n_in,
                              void* d_out, int out_size)
{
    const float* thetas = (const float*)d_in[0];
    const int*   ri     = (const int*)d_in[1];
    const int*   rj     = (const int*)d_in[2];
    float*       out    = (float*)d_out;

    const size_t smem1 = SM_FLOATS * sizeof(float);    // 103712 B
    const size_t smem2 = GSM_FLOATS * sizeof(float);   //  61952 B
    cudaFuncSetAttribute(givens_half_kernel,
                         cudaFuncAttributeMaxDynamicSharedMemorySize, (int)smem1);
    cudaFuncSetAttribute(combine_kernel,
                         cudaFuncAttributeMaxDynamicSharedMemorySize, (int)smem2);

    givens_half_kernel<<<2 * NHEADS, TPB, smem1>>>(thetas, ri, rj);
    combine_kernel<<<2 * NHEADS, GTPB, smem2>>>(out);
}